// round 17
// baseline (speedup 1.0000x reference)
#include <cuda_runtime.h>
#include <cuda_bf16.h>
#include <cstdint>

#define NN   100000
#define NE   1600000
#define NGR  128
#define D_   128
#define DO_  64
#define BN_EPS 1e-5f
#define SCAN_ELEMS 2048
#define NBLK ((NN + SCAN_ELEMS - 1) / SCAN_ELEMS)   // 49

typedef unsigned long long ull;

// ---------------- scratch ----------------
__device__ __align__(16) __nv_bfloat16 g_aggb[(size_t)NN * D_];
__device__ __align__(16) __nv_bfloat16 g_xb [(size_t)NN * D_];
__device__ __align__(16) __nv_bfloat16 g_h1 [(size_t)NN * D_];
__device__ __align__(16) __nv_bfloat16 g_h2 [(size_t)NN * D_];
__device__ __align__(16) __nv_bfloat16 g_hbnb[(size_t)NN * D_];
__device__ __align__(16) float g_bnstats[2 * D_];
__device__ __align__(16) float g_scale[D_];
__device__ __align__(16) float g_shift[D_];
__device__ __align__(16) float g_pool[NGR * DO_];
__device__ __align__(16) int   g_cnt[NGR];
__device__ int g_statctr;
__device__ int g_poolctr;
// CSR scratch
__device__ __align__(16) int g_deg[NN];
__device__ __align__(16) int g_off[NN + 1];
__device__ __align__(16) int g_cur[NN];
__device__ __align__(16) int g_csr[NE];
__device__ int g_bsum[64];
__device__ int g_bscan[64];
// bf16-rounded, pre-swizzled W images
__device__ __align__(16) unsigned char g_whi[6 * 32768];

// ---------------- asm helpers ----------------
__device__ __forceinline__ uint32_t smem_u32(const void* p) {
    uint32_t a;
    asm("{ .reg .u64 t; cvta.to.shared.u64 t, %1; cvt.u32.u64 %0, t; }" : "=r"(a) : "l"(p));
    return a;
}
__device__ __forceinline__ ull add2(ull a, ull b) {
    ull r;
    asm("add.rn.f32x2 %0, %1, %2;" : "=l"(r) : "l"(a), "l"(b));
    return r;
}
__device__ __forceinline__ ull bexp(uint32_t v) {
    return ((ull)(v & 0xffff0000u) << 32) | (ull)(v << 16);
}
__device__ __forceinline__ float4 bexp4(uint2 r) {
    float4 o;
    o.x = __uint_as_float(r.x << 16);
    o.y = __uint_as_float(r.x & 0xffff0000u);
    o.z = __uint_as_float(r.y << 16);
    o.w = __uint_as_float(r.y & 0xffff0000u);
    return o;
}
__device__ __forceinline__ uint32_t pack_bf2(ull p) {
    __nv_bfloat162 b;
    b.x = __float2bfloat16(__uint_as_float((uint32_t)p));
    b.y = __float2bfloat16(__uint_as_float((uint32_t)(p >> 32)));
    return *(uint32_t*)&b;
}
__device__ __forceinline__ void ldsm_x4(uint32_t& r0, uint32_t& r1, uint32_t& r2, uint32_t& r3,
                                        uint32_t addr) {
    asm volatile("ldmatrix.sync.aligned.m8n8.x4.shared.b16 {%0,%1,%2,%3}, [%4];"
                 : "=r"(r0), "=r"(r1), "=r"(r2), "=r"(r3) : "r"(addr));
}
__device__ __forceinline__ void ldsm_x4t(uint32_t& r0, uint32_t& r1, uint32_t& r2, uint32_t& r3,
                                         uint32_t addr) {
    asm volatile("ldmatrix.sync.aligned.m8n8.x4.trans.shared.b16 {%0,%1,%2,%3}, [%4];"
                 : "=r"(r0), "=r"(r1), "=r"(r2), "=r"(r3) : "r"(addr));
}
__device__ __forceinline__ void mma16816(float* c, uint32_t a0, uint32_t a1, uint32_t a2,
                                         uint32_t a3, uint32_t b0, uint32_t b1) {
    asm volatile("mma.sync.aligned.m16n8k16.row.col.f32.bf16.bf16.f32 "
                 "{%0,%1,%2,%3}, {%4,%5,%6,%7}, {%8,%9}, {%0,%1,%2,%3};"
                 : "+f"(c[0]), "+f"(c[1]), "+f"(c[2]), "+f"(c[3])
                 : "r"(a0), "r"(a1), "r"(a2), "r"(a3), "r"(b0), "r"(b1));
}

// ---------------- CSR build ----------------
__global__ void hist_kernel(const int* __restrict__ dst) {
    int i = blockIdx.x * blockDim.x + threadIdx.x;
    if (i < NE) atomicAdd(&g_deg[__ldg(dst + i)], 1);
}
__global__ void scan_pass1() {
    __shared__ int ssum[8];
    int b = blockIdx.x, tid = threadIdx.x;
    int base = b * SCAN_ELEMS + tid * 8;
    int s = 0;
    #pragma unroll
    for (int j = 0; j < 8; j++) { int idx = base + j; s += (idx < NN) ? g_deg[idx] : 0; }
    #pragma unroll
    for (int o = 16; o; o >>= 1) s += __shfl_down_sync(0xffffffffu, s, o);
    if ((tid & 31) == 0) ssum[tid >> 5] = s;
    __syncthreads();
    if (tid == 0) {
        int t = 0;
        #pragma unroll
        for (int i = 0; i < 8; i++) t += ssum[i];
        g_bsum[b] = t;
    }
}
__global__ void scan_pass2() {
    int tid = threadIdx.x;
    int v = (tid < NBLK) ? g_bsum[tid] : 0;
    int incl = v, lane = tid & 31;
    #pragma unroll
    for (int o = 1; o < 32; o <<= 1) {
        int y = __shfl_up_sync(0xffffffffu, incl, o);
        if (lane >= o) incl += y;
    }
    __shared__ int w0;
    if (tid == 31) w0 = incl;
    __syncthreads();
    if (tid >= 32) incl += w0;
    if (tid < 64) g_bscan[tid] = incl - v;
    if (tid == 0) g_off[NN] = NE;
}
__global__ void scan_pass3() {
    int b = blockIdx.x, tid = threadIdx.x;
    int base = b * SCAN_ELEMS + tid * 8;
    int vals[8], t = 0;
    #pragma unroll
    for (int j = 0; j < 8; j++) { vals[j] = (base + j < NN) ? g_deg[base + j] : 0; t += vals[j]; }
    int lane = tid & 31, wid = tid >> 5, incl = t;
    #pragma unroll
    for (int o = 1; o < 32; o <<= 1) {
        int y = __shfl_up_sync(0xffffffffu, incl, o);
        if (lane >= o) incl += y;
    }
    __shared__ int wsum[8], woff[8];
    if (lane == 31) wsum[wid] = incl;
    __syncthreads();
    if (tid == 0) { int a = 0; for (int i = 0; i < 8; i++) { woff[i] = a; a += wsum[i]; } }
    __syncthreads();
    int run = g_bscan[b] + woff[wid] + (incl - t);
    #pragma unroll
    for (int j = 0; j < 8; j++) {
        int idx = base + j;
        if (idx < NN) {
            g_off[idx] = run; g_cur[idx] = run; run += vals[j];
            g_deg[idx] = 0;
        }
    }
}
__global__ void fill_kernel(const int* __restrict__ src, const int* __restrict__ dst) {
    int i = blockIdx.x * blockDim.x + threadIdx.x;
    if (i < NE) {
        int d = __ldg(dst + i);
        int p = atomicAdd(&g_cur[d], 1);
        g_csr[p] = __ldg(src + i);
    }
}

// ---------------- prep: x->bf16, W->bf16 swizzled, pool count histogram ----------------
__global__ void prep_kernel(const float* __restrict__ x,
                            const float* w0, const float* w1, const float* w2,
                            const float* w3, const float* w4, const float* w5,
                            const int* __restrict__ batch)
{
    int i = blockIdx.x * blockDim.x + threadIdx.x;
    if (i < NN * 32) {
        float4 v = __ldg((const float4*)x + i);
        __nv_bfloat162 p0, p1;
        p0.x = __float2bfloat16(v.x); p0.y = __float2bfloat16(v.y);
        p1.x = __float2bfloat16(v.z); p1.y = __float2bfloat16(v.w);
        uint2 o;
        o.x = *(uint32_t*)&p0; o.y = *(uint32_t*)&p1;
        ((uint2*)g_xb)[i] = o;
    }
    if (i < 5 * 16384 + 8192) {
        int seg = i >> 14;
        int t = i & 16383;
        int nout = (seg == 5) ? 64 : 128;
        const float* W = (seg == 0) ? w0 : (seg == 1) ? w1 : (seg == 2) ? w2
                       : (seg == 3) ? w3 : (seg == 4) ? w4 : w5;
        int k = t / nout, n = t % nout;
        float w = __ldg(W + k * nout + n);
        int pos = k * nout + ((((n >> 3) ^ (k & 7)) << 3) | (n & 7));
        ((__nv_bfloat16*)(g_whi + seg * 32768))[pos] = __float2bfloat16(w);
    }
    if (i < NN) atomicAdd(&g_cnt[__ldg(batch + i)], 1);
}

// ---------------- pure-sum gather, bf16 in / bf16 out ----------------
__global__ void gather_bf16_kernel(const __nv_bfloat16* __restrict__ hsrc,
                                   __nv_bfloat16* __restrict__ out)
{
    int n = blockIdx.x * 8 + (threadIdx.x >> 5);
    if (n >= NN) return;
    int lane = threadIdx.x & 31;
    const uint2* __restrict__ hb = (const uint2*)hsrc;

    uint2 s = __ldg(&hb[(size_t)n * 32 + lane]);
    ull a0 = bexp(s.x), b0 = bexp(s.y);
    ull a1 = 0, b1 = 0, a2 = 0, b2 = 0, a3 = 0, b3 = 0;

    int j = g_off[n], e1 = g_off[n + 1];
    for (; j + 4 <= e1; j += 4) {
        int i0 = __ldg(&g_csr[j]);
        int i1 = __ldg(&g_csr[j + 1]);
        int i2 = __ldg(&g_csr[j + 2]);
        int i3 = __ldg(&g_csr[j + 3]);
        uint2 w0 = __ldg(&hb[(size_t)i0 * 32 + lane]);
        uint2 w1 = __ldg(&hb[(size_t)i1 * 32 + lane]);
        uint2 w2 = __ldg(&hb[(size_t)i2 * 32 + lane]);
        uint2 w3 = __ldg(&hb[(size_t)i3 * 32 + lane]);
        a0 = add2(a0, bexp(w0.x)); b0 = add2(b0, bexp(w0.y));
        a1 = add2(a1, bexp(w1.x)); b1 = add2(b1, bexp(w1.y));
        a2 = add2(a2, bexp(w2.x)); b2 = add2(b2, bexp(w2.y));
        a3 = add2(a3, bexp(w3.x)); b3 = add2(b3, bexp(w3.y));
    }
    for (; j < e1; j++) {
        int sidx = __ldg(&g_csr[j]);
        uint2 w = __ldg(&hb[(size_t)sidx * 32 + lane]);
        a0 = add2(a0, bexp(w.x)); b0 = add2(b0, bexp(w.y));
    }
    a0 = add2(add2(a0, a1), add2(a2, a3));
    b0 = add2(add2(b0, b1), add2(b2, b3));
    uint2 o;
    o.x = pack_bf2(a0);
    o.y = pack_bf2(b0);
    ((uint2*)out)[(size_t)n * 32 + lane] = o;
}

// ---------------- BN+ReLU apply: bf16 h -> bf16 hbn ----------------
__global__ void bn_apply_kernel(const __nv_bfloat16* __restrict__ pre)
{
    int i = blockIdx.x * blockDim.x + threadIdx.x;
    if (i >= NN * 32) return;
    int c = (i & 31) << 2;
    float4 v  = bexp4(__ldg((const uint2*)pre + i));
    float4 sc = *(const float4*)(g_scale + c);
    float4 sh = *(const float4*)(g_shift + c);
    v.x = fmaxf(fmaf(v.x, sc.x, sh.x), 0.f);
    v.y = fmaxf(fmaf(v.y, sc.y, sh.y), 0.f);
    v.z = fmaxf(fmaf(v.z, sc.z, sh.z), 0.f);
    v.w = fmaxf(fmaf(v.w, sc.w, sh.w), 0.f);
    __nv_bfloat162 p0, p1;
    p0.x = __float2bfloat16(v.x); p0.y = __float2bfloat16(v.y);
    p1.x = __float2bfloat16(v.z); p1.y = __float2bfloat16(v.w);
    uint2 o;
    o.x = *(uint32_t*)&p0; o.y = *(uint32_t*)&p1;
    ((uint2*)g_hbnb)[i] = o;
}

// ---------------- 1-term mma_loop: A @ B, both bf16 ----------------
template<int NT>
__device__ __forceinline__ void mma_loop1(uint32_t sb, uint32_t aOff, uint32_t bOff,
                                          int wid, int lane, float acc[][4])
{
    const int la = lane & 15;
    const int lb = lane >> 4;
    const int l7 = lane & 7;
    const int BR = NT * 16;
    const uint32_t aRow = (uint32_t)((wid * 16 + la) * 256);
    const uint32_t bRow = (uint32_t)(la * BR);
    #pragma unroll 2
    for (int k0 = 0; k0 < 128; k0 += 16) {
        uint32_t kc = (uint32_t)((k0 >> 3) + lb);
        uint32_t aoff = aRow + ((kc ^ (uint32_t)l7) << 4);
        uint32_t a0, a1, a2, a3;
        ldsm_x4(a0, a1, a2, a3, sb + aOff + aoff);
        uint32_t bbase = (uint32_t)(k0 * BR) + bRow;
        #pragma unroll
        for (int nt = 0; nt < NT; nt += 2) {
            uint32_t boff = bbase + ((((uint32_t)(nt + lb)) ^ (uint32_t)l7) << 4);
            uint32_t bh0, bh1, bh2, bh3;
            ldsm_x4t(bh0, bh1, bh2, bh3, sb + bOff + boff);
            mma16816(acc[nt],     a0, a1, a2, a3, bh0, bh1);
            mma16816(acc[nt + 1], a0, a1, a2, a3, bh2, bh3);
        }
    }
}

// ---------------- fused 2-GEMM MLP + BN stats + last-block finalize ----------------
template<int NOUT>
__global__ __launch_bounds__(256, 2)
void mlp_mma(const __nv_bfloat16* __restrict__ A,
             const unsigned char* __restrict__ w1h, const float* __restrict__ b1,
             const unsigned char* __restrict__ w2h, const float* __restrict__ b2,
             __nv_bfloat16* __restrict__ out,
             const float* __restrict__ gamma, const float* __restrict__ beta)
{
    constexpr int NT2  = NOUT / 8;
    constexpr int AOF  = 0;
    constexpr int B1OF = 32768;
    constexpr int B2OF = 65536;

    extern __shared__ __align__(16) char smem[];
    const uint32_t sb = smem_u32(smem);
    const int tid  = threadIdx.x;
    const int wid  = tid >> 5;
    const int lane = tid & 31;
    const int row0 = blockIdx.x * 128;
    __shared__ int isLast;

    // B tiles
    {
        const float4* s1 = (const float4*)w1h;
        float4* d1 = (float4*)(smem + B1OF);
        #pragma unroll
        for (int i = tid; i < 2048; i += 256) d1[i] = s1[i];
        const float4* s3 = (const float4*)w2h;
        float4* d3 = (float4*)(smem + B2OF);
        #pragma unroll
        for (int i = tid; i < NOUT * 16; i += 256) d3[i] = s3[i];
    }
    // A tile: bf16 rows, swizzled 16B chunks
    for (int i = tid; i < 2048; i += 256) {
        int r = i >> 4, c = i & 15;
        int gr = row0 + r;
        uint4 v = make_uint4(0, 0, 0, 0);
        if (gr < NN) v = __ldg((const uint4*)(A + (size_t)gr * 128) + c);
        uint32_t off = (uint32_t)(r * 256 + ((c ^ (r & 7)) << 4));
        *(uint4*)(smem + AOF + off) = v;
    }
    __syncthreads();

    // stage 1
    float acc[16][4];
    #pragma unroll
    for (int t = 0; t < 16; t++)
        #pragma unroll
        for (int e = 0; e < 4; e++) acc[t][e] = 0.f;
    mma_loop1<16>(sb, AOF, B1OF, wid, lane, acc);
    __syncthreads();

    // epilogue 1: bias+ReLU, bf16, write back into A buffer
    {
        int rr1 = wid * 16 + (lane >> 2);
        int rr2 = rr1 + 8;
        uint32_t cb1 = (uint32_t)(rr1 * 256);
        uint32_t cb2 = (uint32_t)(rr2 * 256);
        int sw1 = (rr1 & 7), sw2 = (rr2 & 7);
        int cpos = (lane & 3) * 4;
        #pragma unroll
        for (int nt = 0; nt < 16; nt++) {
            int col = nt * 8 + (lane & 3) * 2;
            float2 bb = __ldg((const float2*)(b1 + col));
            float v0 = fmaxf(acc[nt][0] + bb.x, 0.f);
            float v1 = fmaxf(acc[nt][1] + bb.y, 0.f);
            float v2 = fmaxf(acc[nt][2] + bb.x, 0.f);
            float v3 = fmaxf(acc[nt][3] + bb.y, 0.f);
            __nv_bfloat162 h2;
            h2.x = __float2bfloat16(v0);
            h2.y = __float2bfloat16(v1);
            uint32_t o1 = cb1 + ((uint32_t)(nt ^ sw1) << 4) + cpos;
            *(uint32_t*)(smem + AOF + o1) = *(uint32_t*)&h2;
            h2.x = __float2bfloat16(v2);
            h2.y = __float2bfloat16(v3);
            uint32_t o2 = cb2 + ((uint32_t)(nt ^ sw2) << 4) + cpos;
            *(uint32_t*)(smem + AOF + o2) = *(uint32_t*)&h2;
        }
    }
    __syncthreads();

    // stage 2
    float acc2[NT2][4];
    #pragma unroll
    for (int t = 0; t < NT2; t++)
        #pragma unroll
        for (int e = 0; e < 4; e++) acc2[t][e] = 0.f;
    mma_loop1<NT2>(sb, AOF, B2OF, wid, lane, acc2);
    __syncthreads();    // all warps done reading A; AOF region reusable for stats

    // epilogue 2: write output + per-column stats (shfl-reduce, smem slabs, no hot atomics)
    float* ss = (float*)(smem + AOF);            // [8][NOUT] sums
    float* sq = ss + 8 * NOUT;                   // [8][NOUT] sumsq  (8 KB total max)
    int r1 = row0 + wid * 16 + (lane >> 2);
    int r2 = r1 + 8;
    bool g1, g2;
    g1 = (r1 < NN); g2 = (r2 < NN);
    #pragma unroll
    for (int nt = 0; nt < NT2; nt++) {
        int col = nt * 8 + (lane & 3) * 2;
        float2 bb = __ldg((const float2*)(b2 + col));
        float v0 = acc2[nt][0] + bb.x;
        float v1 = acc2[nt][1] + bb.y;
        float v2 = acc2[nt][2] + bb.x;
        float v3 = acc2[nt][3] + bb.y;
        if (g1) {
            __nv_bfloat162 p;
            p.x = __float2bfloat16(v0); p.y = __float2bfloat16(v1);
            *(uint32_t*)(out + (size_t)r1 * NOUT + col) = *(uint32_t*)&p;
        }
        if (g2) {
            __nv_bfloat162 p;
            p.x = __float2bfloat16(v2); p.y = __float2bfloat16(v3);
            *(uint32_t*)(out + (size_t)r2 * NOUT + col) = *(uint32_t*)&p;
        }
        float cs0 = (g1 ? v0 : 0.f) + (g2 ? v2 : 0.f);
        float cs1 = (g1 ? v1 : 0.f) + (g2 ? v3 : 0.f);
        float cq0 = (g1 ? v0 * v0 : 0.f) + (g2 ? v2 * v2 : 0.f);
        float cq1 = (g1 ? v1 * v1 : 0.f) + (g2 ? v3 * v3 : 0.f);
        #pragma unroll
        for (int o = 4; o < 32; o <<= 1) {
            cs0 += __shfl_xor_sync(0xffffffffu, cs0, o);
            cs1 += __shfl_xor_sync(0xffffffffu, cs1, o);
            cq0 += __shfl_xor_sync(0xffffffffu, cq0, o);
            cq1 += __shfl_xor_sync(0xffffffffu, cq1, o);
        }
        if ((lane >> 2) == 0) {      // lanes 0..3 hold column totals
            ss[wid * NOUT + col]     = cs0;
            ss[wid * NOUT + col + 1] = cs1;
            sq[wid * NOUT + col]     = cq0;
            sq[wid * NOUT + col + 1] = cq1;
        }
    }
    __syncthreads();
    // cross-warp reduce + one global atomic per column
    if (tid < NOUT) {
        float t = 0.f;
        #pragma unroll
        for (int w = 0; w < 8; w++) t += ss[w * NOUT + tid];
        atomicAdd(&g_bnstats[tid], t);
    } else if (tid >= 128 && tid < 128 + NOUT) {
        int c = tid - 128;
        float t = 0.f;
        #pragma unroll
        for (int w = 0; w < 8; w++) t += sq[w * NOUT + c];
        atomicAdd(&g_bnstats[NOUT + c], t);
    }
    __threadfence();
    if (tid == 0) isLast = (atomicAdd(&g_statctr, 1) == (int)gridDim.x - 1);
    __syncthreads();
    if (isLast) {
        __threadfence();
        if (tid < NOUT) {
            const float invN = 1.0f / (float)NN;
            float sv = g_bnstats[tid];
            float qv = g_bnstats[NOUT + tid];
            float mu  = sv * invN;
            float var = qv * invN - mu * mu;
            float s   = gamma[tid] * rsqrtf(var + BN_EPS);
            g_scale[tid] = s;
            g_shift[tid] = beta[tid] - mu * s;
            g_bnstats[tid] = 0.f;
            g_bnstats[NOUT + tid] = 0.f;
        }
        if (tid == 0) g_statctr = 0;
    }
}

// ---------------- pooling (BN+ReLU fused) + last-block finalize ----------------
__global__ void pool_sum_kernel(const __nv_bfloat16* __restrict__ pre,
                                const int* __restrict__ batch,
                                float* __restrict__ outp)
{
    int t = blockIdx.x * blockDim.x + threadIdx.x;
    __shared__ int isLast;
    if (t < NN * 16) {
        int n = t >> 4, q = t & 15;
        int c = q << 2;
        int b = __ldg(batch + n);
        float4 v  = bexp4(__ldg((const uint2*)pre + (size_t)n * 16 + q));
        float4 sc = *(const float4*)(g_scale + c);
        float4 sh = *(const float4*)(g_shift + c);
        v.x = fmaxf(fmaf(v.x, sc.x, sh.x), 0.f);
        v.y = fmaxf(fmaf(v.y, sc.y, sh.y), 0.f);
        v.z = fmaxf(fmaf(v.z, sc.z, sh.z), 0.f);
        v.w = fmaxf(fmaf(v.w, sc.w, sh.w), 0.f);
        float* p = g_pool + b * DO_ + c;
        asm volatile("red.global.add.v4.f32 [%0], {%1, %2, %3, %4};"
                     :: "l"(p), "f"(v.x), "f"(v.y), "f"(v.z), "f"(v.w) : "memory");
    }
    __threadfence();
    if (threadIdx.x == 0) isLast = (atomicAdd(&g_poolctr, 1) == (int)gridDim.x - 1);
    __syncthreads();
    if (isLast) {
        __threadfence();
        for (int i = threadIdx.x; i < NGR * DO_; i += 256) {
            int g = i >> 6;
            int cv = g_cnt[g];
            float c = (float)(cv > 0 ? cv : 1);
            outp[i] = g_pool[i] / c;
            g_pool[i] = 0.f;
        }
        __syncthreads();
        for (int i = threadIdx.x; i < NGR; i += 256) g_cnt[i] = 0;
        if (threadIdx.x == 0) g_poolctr = 0;
    }
}

// ---------------- launcher ----------------
extern "C" void kernel_launch(void* const* d_in, const int* in_sizes, int n_in,
                              void* d_out, int out_size)
{
    const float* x     = (const float*)d_in[0];
    const int*   ei    = (const int*)d_in[1];
    const int*   batch = (const int*)d_in[2];
    const float *wA[3], *bA[3], *wB[3], *bB[3], *gam[3], *bet[3];
    for (int l = 0; l < 3; l++) {
        wA[l]  = (const float*)d_in[3 + 6*l + 0];
        bA[l]  = (const float*)d_in[3 + 6*l + 1];
        wB[l]  = (const float*)d_in[3 + 6*l + 2];
        bB[l]  = (const float*)d_in[3 + 6*l + 3];
        gam[l] = (const float*)d_in[3 + 6*l + 4];
        bet[l] = (const float*)d_in[3 + 6*l + 5];
    }
    const int* src = ei;
    const int* dst = ei + NE;

    __nv_bfloat16 *aggb, *xb, *h1, *h2, *hbnb;
    unsigned char *whi;
    cudaGetSymbolAddress((void**)&aggb, g_aggb);
    cudaGetSymbolAddress((void**)&xb,   g_xb);
    cudaGetSymbolAddress((void**)&h1,   g_h1);
    cudaGetSymbolAddress((void**)&h2,   g_h2);
    cudaGetSymbolAddress((void**)&hbnb, g_hbnb);
    cudaGetSymbolAddress((void**)&whi,  g_whi);

    constexpr int SMF128 = 32768 + 32768 + 32768;  // 98304
    constexpr int SMF64  = 32768 + 32768 + 16384;  // 81920
    cudaFuncSetAttribute(mlp_mma<128>, cudaFuncAttributeMaxDynamicSharedMemorySize, SMF128);
    cudaFuncSetAttribute(mlp_mma<64>,  cudaFuncAttributeMaxDynamicSharedMemorySize, SMF64);

    const int GB = (NN + 127) / 128;   // 782
    const int EG = (NE + 255) / 256;
    const int GG = (NN + 7) / 8;
    const int AG = (NN * 32 + 255) / 256;

    // ---- CSR build ----
    hist_kernel<<<EG, 256>>>(dst);
    scan_pass1<<<NBLK, 256>>>();
    scan_pass2<<<1, 64>>>();
    scan_pass3<<<NBLK, 256>>>();
    fill_kernel<<<EG, 256>>>(src, dst);

    // ---- prep: x->bf16, W->bf16 swizzled, pool count ----
    prep_kernel<<<AG, 256>>>(x, wA[0], wB[0], wA[1], wB[1], wA[2], wB[2], batch);

    // ---- layer 0 ----
    gather_bf16_kernel<<<GG, 256>>>(xb, aggb);
    mlp_mma<128><<<GB, 256, SMF128>>>(aggb, whi + 0*32768, bA[0], whi + 1*32768, bB[0],
                                      h1, gam[0], bet[0]);
    bn_apply_kernel<<<AG, 256>>>(h1);

    // ---- layer 1 ----
    gather_bf16_kernel<<<GG, 256>>>(hbnb, aggb);
    mlp_mma<128><<<GB, 256, SMF128>>>(aggb, whi + 2*32768, bA[1], whi + 3*32768, bB[1],
                                      h2, gam[1], bet[1]);
    bn_apply_kernel<<<AG, 256>>>(h2);

    // ---- layer 2 ----
    gather_bf16_kernel<<<GG, 256>>>(hbnb, aggb);
    mlp_mma<64><<<GB, 256, SMF64>>>(aggb, whi + 4*32768, bA[2], whi + 5*32768, bB[2],
                                    h1, gam[2], bet[2]);

    // ---- global mean pool (BN+ReLU fused, last-block finalize) ----
    pool_sum_kernel<<<(NN * 16 + 255)/256, 256>>>(h1, batch, (float*)d_out);
}